// round 12
// baseline (speedup 1.0000x reference)
#include <cuda_runtime.h>
#include <math.h>
#include <cstdint>

#define NTOK 131072      // B*S tokens
#define KC   128         // memory bank size
#define DD   192         // projection dim
#define TOKT 64          // tokens per block in sim kernel
#define NBLK (NTOK / TOKT)   // 2048
#define SKB  2048        // sinkhorn pass grid
#define BPITCH 36        // token-row pitch (floats) in B smem

typedef unsigned int u32;

// ---------------- scratch (static __device__: no allocation) ----------------
__device__ float g_E[(size_t)NTOK * KC];        // exp(sim/0.05), [token][k], 64 MiB
__device__ u32   g_afrag_hi[24 * 8 * 32 * 4];   // A frags [kc][mt][t][reg], tf32 hi
__device__ u32   g_afrag_lo[24 * 8 * 32 * 4];   // tf32 lo
__device__ float g_memn[KC * DD];               // normalized codes fp32 (exact path)
__device__ float g_gated[KC * DD];              // precomputed GLU(mem_bank) table
__device__ float g_cinv[KC];                    // per-code inv norm
__device__ float g_linv[KC * 2 * DD];           // GLU linear out
__device__ float g_a[KC];                       // current row scaling
__device__ float g_la[KC];                      // ln(a)
__device__ float g_partA[NBLK * KC];            // simexp rowsum partials
__device__ float g_partB[SKB * KC];             // sinkhorn pass partials

__device__ __forceinline__ u32 f2tf32(float f) {
    u32 r; asm("cvt.rna.tf32.f32 %0, %1;" : "=r"(r) : "f"(f)); return r;
}
__device__ __forceinline__ void mma_tf32(float* d, const u32* a, u32 b0, u32 b1) {
    asm volatile(
        "mma.sync.aligned.m16n8k8.row.col.f32.tf32.tf32.f32 "
        "{%0,%1,%2,%3}, {%4,%5,%6,%7}, {%8,%9}, {%0,%1,%2,%3};"
        : "+f"(d[0]), "+f"(d[1]), "+f"(d[2]), "+f"(d[3])
        : "r"(a[0]), "r"(a[1]), "r"(a[2]), "r"(a[3]), "r"(b0), "r"(b1));
}

// ---------------- prep (split into 5 launches so simexp = launch #5) ---------
__global__ void prep_norm_kernel(const float* __restrict__ mb) {
    __shared__ float sq[DD];
    int k = blockIdx.x, t = threadIdx.x;
    float v = mb[k * DD + t];
    sq[t] = v * v;
    __syncthreads();
    if (t == 0) {
        float ss = 0.f;
        for (int d = 0; d < DD; d++) ss += sq[d];
        g_cinv[k] = 1.0f / sqrtf(fmaxf(ss, 1e-12f));
    }
}
__global__ void prep_frag_kernel(const float* __restrict__ mb) {
    int m = blockIdx.x, t = threadIdx.x;
    float v = mb[m * DD + t] * g_cinv[m];
    g_memn[m * DD + t] = v;
    int kc = t >> 3, kk = t & 7;
    int mt = m >> 4, rin = m & 15;
    int reg = ((rin >> 3) & 1) | ((kk >> 2) << 1);
    int tt  = (rin & 7) * 4 + (kk & 3);
    int idx = ((kc * 8 + mt) * 32 + tt) * 4 + reg;
    u32 hi = f2tf32(v);
    g_afrag_hi[idx] = hi;
    g_afrag_lo[idx] = f2tf32(v - __uint_as_float(hi));
}
__global__ void prep_lin_kernel(const float* __restrict__ mb,
                                const float* __restrict__ gw,
                                const float* __restrict__ gb, int half) {
    __shared__ float row[DD];
    int k = blockIdx.x, t = threadIdx.x;
    row[t] = mb[k * DD + t];
    __syncthreads();
    int col = half * DD + t;
    float acc = gb[col];
    for (int j = 0; j < DD; j++) acc = fmaf(row[j], gw[j * (2 * DD) + col], acc);
    g_linv[k * (2 * DD) + col] = acc;
}
__global__ void prep_gated_kernel() {
    int k = blockIdx.x, t = threadIdx.x;
    float lin = g_linv[k * (2 * DD) + t];
    float gate = g_linv[k * (2 * DD) + DD + t];
    g_gated[k * DD + t] = lin * (1.0f / (1.0f + expf(-gate)));
}

// ---------------- sim GEMM tf32 3-pass, 128 codes x 64 tokens, pipelined -----
// 8 warps: warp w -> codes [32*(w>>1), +32), tokens [32*(w&1), +32)
// smem: afh 16K | afl 16K | xhi 9216 | xlo 9216 | sq 1K | invn 256 | ps 1K
#define SX_AFH 0
#define SX_AFL 16384
#define SX_XHI 32768
#define SX_XLO 41984
#define SX_SQ  51200
#define SX_INV 52224
#define SX_PS  52480
#define SX_TOT 53504
__global__ __launch_bounds__(256, 2)
void simexp_mma_kernel(const float* __restrict__ x) {
    extern __shared__ char dyn[];
    u32*   afh  = (u32*)(dyn + SX_AFH);
    u32*   afl  = (u32*)(dyn + SX_AFL);
    u32*   xhi  = (u32*)(dyn + SX_XHI);
    u32*   xlo  = (u32*)(dyn + SX_XLO);
    float* sq   = (float*)(dyn + SX_SQ);
    float* invn = (float*)(dyn + SX_INV);
    float* ps   = (float*)(dyn + SX_PS);

    int tid = threadIdx.x, lane = tid & 31, w = tid >> 5;
    int mt2 = w >> 1;           // code block (32 codes)
    int nt4 = w & 1;            // token half (32 tokens)
    int tok0 = blockIdx.x * TOKT;

    int tk = tid >> 2, h = tid & 3;   // staging: token, 8-float group
    float ss = 0.f;

    float acc[2][4][4];
    #pragma unroll
    for (int mi = 0; mi < 2; mi++)
        #pragma unroll
        for (int nt = 0; nt < 4; nt++)
            #pragma unroll
            for (int r = 0; r < 4; r++) acc[mi][nt][r] = 0.f;

    const uint4* srcA_h = (const uint4*)g_afrag_hi;
    const uint4* srcA_l = (const uint4*)g_afrag_lo;

    // register preload buffers (software pipeline, single smem buffer)
    uint4  pAh[4], pAl[4];
    float4 pX[2];
    #pragma unroll
    for (int i = 0; i < 4; i++) {
        pAh[i] = srcA_h[tid + 256 * i];
        pAl[i] = srcA_l[tid + 256 * i];
    }
    {
        const float4* sx = (const float4*)(x + (size_t)(tok0 + tk) * DD + h * 8);
        pX[0] = sx[0]; pX[1] = sx[1];
    }

    for (int c = 0; c < 6; c++) {
        // store preloaded chunk c into smem (+ tf32 split for X, sumsq)
        #pragma unroll
        for (int i = 0; i < 4; i++) {
            ((uint4*)afh)[tid + 256 * i] = pAh[i];
            ((uint4*)afl)[tid + 256 * i] = pAl[i];
        }
        {
            float vv[8] = {pX[0].x, pX[0].y, pX[0].z, pX[0].w,
                           pX[1].x, pX[1].y, pX[1].z, pX[1].w};
            u32 hhi[8], llo[8];
            #pragma unroll
            for (int j = 0; j < 8; j++) {
                float v = vv[j];
                ss = fmaf(v, v, ss);
                hhi[j] = f2tf32(v);
                llo[j] = f2tf32(v - __uint_as_float(hhi[j]));
            }
            uint4* dh = (uint4*)&xhi[tk * BPITCH + h * 8];
            uint4* dl = (uint4*)&xlo[tk * BPITCH + h * 8];
            dh[0] = make_uint4(hhi[0], hhi[1], hhi[2], hhi[3]);
            dh[1] = make_uint4(hhi[4], hhi[5], hhi[6], hhi[7]);
            dl[0] = make_uint4(llo[0], llo[1], llo[2], llo[3]);
            dl[1] = make_uint4(llo[4], llo[5], llo[6], llo[7]);
        }
        __syncthreads();

        // preload chunk c+1 (global latency overlaps the MMAs below)
        if (c < 5) {
            #pragma unroll
            for (int i = 0; i < 4; i++) {
                pAh[i] = srcA_h[(c + 1) * 1024 + tid + 256 * i];
                pAl[i] = srcA_l[(c + 1) * 1024 + tid + 256 * i];
            }
            const float4* sx = (const float4*)(x + (size_t)(tok0 + tk) * DD + (c + 1) * 32 + h * 8);
            pX[0] = sx[0]; pX[1] = sx[1];
        }

        #pragma unroll
        for (int ks = 0; ks < 4; ks++) {
            u32 ah[2][4], al[2][4];
            #pragma unroll
            for (int mi = 0; mi < 2; mi++) {
                int mt = mt2 * 2 + mi;
                uint4 th = *(const uint4*)(afh + ((ks * 8 + mt) * 32 + lane) * 4);
                uint4 tl = *(const uint4*)(afl + ((ks * 8 + mt) * 32 + lane) * 4);
                ah[mi][0] = th.x; ah[mi][1] = th.y; ah[mi][2] = th.z; ah[mi][3] = th.w;
                al[mi][0] = tl.x; al[mi][1] = tl.y; al[mi][2] = tl.z; al[mi][3] = tl.w;
            }
            #pragma unroll
            for (int nt = 0; nt < 4; nt++) {
                int nrow = nt4 * 32 + nt * 8 + (lane >> 2);
                int kcol = ks * 8 + (lane & 3);
                u32 bh0 = xhi[nrow * BPITCH + kcol];
                u32 bh1 = xhi[nrow * BPITCH + kcol + 4];
                u32 bl0 = xlo[nrow * BPITCH + kcol];
                u32 bl1 = xlo[nrow * BPITCH + kcol + 4];
                #pragma unroll
                for (int mi = 0; mi < 2; mi++) {
                    mma_tf32(acc[mi][nt], ah[mi], bh0, bh1);   // hi*hi
                    mma_tf32(acc[mi][nt], ah[mi], bl0, bl1);   // hi*lo
                    mma_tf32(acc[mi][nt], al[mi], bh0, bh1);   // lo*hi
                }
            }
        }
        __syncthreads();
    }

    // per-token inv norms (4 staging threads per token)
    sq[tid] = ss;
    __syncthreads();
    if (tid < TOKT)
        invn[tid] = 1.0f / sqrtf(fmaxf(sq[4 * tid] + sq[4 * tid + 1] +
                                       sq[4 * tid + 2] + sq[4 * tid + 3], 1e-12f));
    __syncthreads();

    // epilogue: E = expf(20*sim*invn), store + rowsum partials
    float racc[4] = {0.f, 0.f, 0.f, 0.f};   // [mi*2 + rowhalf]
    #pragma unroll
    for (int mi = 0; mi < 2; mi++)
        #pragma unroll
        for (int nt = 0; nt < 4; nt++)
            #pragma unroll
            for (int r = 0; r < 4; r++) {
                int code = mt2 * 32 + mi * 16 + (lane >> 2) + ((r >> 1) << 3);
                int n = nt4 * 32 + nt * 8 + (lane & 3) * 2 + (r & 1);
                float e = expf(acc[mi][nt][r] * (20.0f * invn[n]));
                g_E[(size_t)(tok0 + n) * KC + code] = e;
                racc[mi * 2 + (r >> 1)] += e;
            }
    #pragma unroll
    for (int q = 0; q < 4; q++) {
        racc[q] += __shfl_xor_sync(0xffffffffu, racc[q], 1);
        racc[q] += __shfl_xor_sync(0xffffffffu, racc[q], 2);
    }
    if ((lane & 3) == 0) {
        #pragma unroll
        for (int q = 0; q < 4; q++) {
            int cl = (q >> 1) * 16 + (q & 1) * 8 + (lane >> 2);   // mi*16 + rh*8 + row
            ps[w * 32 + cl] = racc[q];
        }
    }
    __syncthreads();
    if (tid < KC) {
        int q = tid >> 5;
        float s = ps[(2 * q) * 32 + (tid & 31)] + ps[(2 * q + 1) * 32 + (tid & 31)];
        g_partA[blockIdx.x * KC + tid] = s;
    }
}

// ---------------- reduce partials (coalesced, 1 block) -----------------------
__global__ void reduce_part_kernel(int which) {
    const float* part = which ? g_partB : g_partA;
    __shared__ float sm[1024];
    int tid = threadIdx.x;
    int k = tid & 127, g = tid >> 7;          // 8 groups of 256 rows
    float s = 0.f;
    #pragma unroll 4
    for (int b = g * 256; b < g * 256 + 256; b++)
        s += part[b * KC + k];
    sm[tid] = s;
    __syncthreads();
    if (tid < KC) {
        float t = 0.f;
        #pragma unroll
        for (int gg = 0; gg < 8; gg++) t += sm[tid + 128 * gg];
        g_a[tid] = 1.0f / t;
        g_la[tid] = -logf(t);
    }
}

// ---------------- fused Sinkhorn pass ----------------------------------------
__global__ void sinkhorn_pass_kernel() {
    __shared__ float ps[8 * KC];
    int tid = threadIdx.x, lane = tid & 31, w = tid >> 5;
    int g = blockIdx.x * 8 + w;
    float4 av = *reinterpret_cast<const float4*>(&g_a[lane * 4]);
    size_t base = (size_t)g * 8 * KC;
    float4 e[8];
    #pragma unroll
    for (int i = 0; i < 8; i++)
        e[i] = *reinterpret_cast<const float4*>(&g_E[base + (size_t)i * KC + lane * 4]);
    float r0 = 0.f, r1 = 0.f, r2 = 0.f, r3 = 0.f;
    #pragma unroll
    for (int i = 0; i < 8; i++) {
        float s = e[i].x * av.x + e[i].y * av.y + e[i].z * av.z + e[i].w * av.w;
        #pragma unroll
        for (int o = 16; o > 0; o >>= 1) s += __shfl_xor_sync(0xffffffffu, s, o);
        float b = 1.0f / s;
        r0 = fmaf(e[i].x, b, r0); r1 = fmaf(e[i].y, b, r1);
        r2 = fmaf(e[i].z, b, r2); r3 = fmaf(e[i].w, b, r3);
    }
    ps[w * KC + lane * 4 + 0] = r0;
    ps[w * KC + lane * 4 + 1] = r1;
    ps[w * KC + lane * 4 + 2] = r2;
    ps[w * KC + lane * 4 + 3] = r3;
    __syncthreads();
    if (tid < KC) {
        float s = 0.f;
        #pragma unroll
        for (int ww = 0; ww < 8; ww++) s += ps[ww * KC + tid];
        g_partB[blockIdx.x * KC + tid] = s;
    }
}

// ---------------- argmax (top-2 guarded) + gather + residual avg -------------
__global__ void output_kernel(const float* __restrict__ x, float* __restrict__ out) {
    int tid = threadIdx.x, lane = tid & 31, w = tid >> 5;
    int g = blockIdx.x * 8 + w;
    float4 av = *reinterpret_cast<const float4*>(&g_a[lane * 4]);
    float4 e[8];
    #pragma unroll
    for (int i = 0; i < 8; i++)
        e[i] = *reinterpret_cast<const float4*>(&g_E[(size_t)(g * 8 + i) * KC + lane * 4]);
    for (int i = 0; i < 8; i++) {
        int n = g * 8 + i;
        float v[4] = {e[i].x * av.x, e[i].y * av.y, e[i].z * av.z, e[i].w * av.w};
        float b1 = v[0]; int k1 = lane * 4; float b2 = -1.f;
        #pragma unroll
        for (int j = 1; j < 4; j++) {
            int kk = lane * 4 + j;
            if (v[j] > b1 || (v[j] == b1 && kk < k1)) { b2 = b1; b1 = v[j]; k1 = kk; }
            else b2 = fmaxf(b2, v[j]);
        }
        #pragma unroll
        for (int o = 16; o > 0; o >>= 1) {
            float ov1 = __shfl_xor_sync(0xffffffffu, b1, o);
            int   ok1 = __shfl_xor_sync(0xffffffffu, k1, o);
            float ov2 = __shfl_xor_sync(0xffffffffu, b2, o);
            if (ov1 > b1 || (ov1 == b1 && ok1 < k1)) {
                b2 = fmaxf(b1, ov2); b1 = ov1; k1 = ok1;
            } else {
                if (!(ov1 == b1 && ok1 == k1)) b2 = fmaxf(b2, ov1);
                b2 = fmaxf(b2, ov2);
            }
        }
        int bk = k1;
        if (b2 >= b1 * 0.9999f) {   // near-tie -> exact fp32 recompute (rare)
            const float* xp = x + (size_t)n * DD;
            float dot[4] = {0.f, 0.f, 0.f, 0.f};
            float ssq = 0.f;
            for (int d = 0; d < DD; d++) {
                float xv = xp[d];
                ssq = fmaf(xv, xv, ssq);
                #pragma unroll
                for (int j = 0; j < 4; j++)
                    dot[j] = fmaf(xv, g_memn[(lane * 4 + j) * DD + d], dot[j]);
            }
            float inv = 1.0f / sqrtf(fmaxf(ssq, 1e-12f));
            float sb = -1e30f; int sk = 0;
            #pragma unroll
            for (int j = 0; j < 4; j++) {
                float sc = 20.0f * dot[j] * inv + g_la[lane * 4 + j];
                int kk = lane * 4 + j;
                if (sc > sb || (sc == sb && kk < sk)) { sb = sc; sk = kk; }
            }
            #pragma unroll
            for (int o = 16; o > 0; o >>= 1) {
                float ov = __shfl_xor_sync(0xffffffffu, sb, o);
                int   ok = __shfl_xor_sync(0xffffffffu, sk, o);
                if (ov > sb || (ov == sb && ok < sk)) { sb = ov; sk = ok; }
            }
            bk = sk;
        }
        const float* gp = g_gated + (size_t)bk * DD;
        const float* xp = x + (size_t)n * DD;
        float* op = out + (size_t)n * DD;
        #pragma unroll
        for (int m = 0; m < 6; m++) {
            int d = lane + 32 * m;
            op[d] = (xp[d] + gp[d]) * 0.5f;
        }
    }
}

// ---------------- launch ------------------------------------------------------
extern "C" void kernel_launch(void* const* d_in, const int* in_sizes, int n_in,
                              void* d_out, int out_size) {
    const float* proj = (const float*)d_in[0];   // [64,2048,192]
    const float* mb   = (const float*)d_in[1];   // [128,192]
    const float* gw   = (const float*)d_in[2];   // [192,384]
    const float* gb   = (const float*)d_in[3];   // [384]
    float* out = (float*)d_out;

    cudaFuncSetAttribute(simexp_mma_kernel,
                         cudaFuncAttributeMaxDynamicSharedMemorySize, SX_TOT);

    prep_norm_kernel<<<KC, DD>>>(mb);            // launch 0
    prep_frag_kernel<<<KC, DD>>>(mb);            // launch 1
    prep_lin_kernel<<<KC, DD>>>(mb, gw, gb, 0);  // launch 2
    prep_lin_kernel<<<KC, DD>>>(mb, gw, gb, 1);  // launch 3
    prep_gated_kernel<<<KC, DD>>>();             // launch 4
    simexp_mma_kernel<<<NBLK, 256, SX_TOT>>>(proj);  // launch 5 <- ncu profiles this
    reduce_part_kernel<<<1, 1024>>>(0);          // a1
    sinkhorn_pass_kernel<<<SKB, 256>>>();        // b1 -> partials
    reduce_part_kernel<<<1, 1024>>>(1);          // a2
    sinkhorn_pass_kernel<<<SKB, 256>>>();        // b2 -> partials
    reduce_part_kernel<<<1, 1024>>>(1);          // a3
    output_kernel<<<NTOK / 64, 256>>>(proj, out);
}